// round 16
// baseline (speedup 1.0000x reference)
#include <cuda_runtime.h>

#define NC 24
#define LH 256
#define LW 256
#define PLANE (LH*LW)
#define R 8
#define EPSF 1e-4f
#define KROWS 4                 // LR rows per AB block
#define HSROW 272               // 8 zero-halo + 256 + 8 zero-halo

// scratch (allocation-free rule: __device__ globals)
__device__ float2 g_AB[NC*PLANE];   // {A, B}

// ---------------------------------------------------------------------------
// Kernel 1 (k_AB): A,B coefficients for 4 LR rows per block.
//   Stage V: per-column vertical truncated sliding window over raw I,p
//            -> 4 vsum rows (stats I,P,IP,II) in zero-padded smem.
//   Stage H: horizontal 17-tap running-sum windows + count div + solve;
//            exactly 1 unit (4 columns) per thread -> write g_AB.
// Grid = (64, NC), 256 threads.
// ---------------------------------------------------------------------------
__global__ void __launch_bounds__(256) k_AB(
    const float* __restrict__ p, const float* __restrict__ I)
{
    __shared__ __align__(16) float vsI [KROWS][HSROW];
    __shared__ __align__(16) float vsP [KROWS][HSROW];
    __shared__ __align__(16) float vsIP[KROWS][HSROW];
    __shared__ __align__(16) float vsII[KROWS][HSROW];

    const int mb = blockIdx.x;            // 0..63
    const int pl = blockIdx.y;
    const int t  = threadIdx.x;
    const int k0 = mb << 2;

    // zero the horizontal halos (KROWS rows x 16 floats x 4 stats)
    if (t < KROWS*16) {
        const int row = t >> 4, h = t & 15;
        const int idx = (h < 8 ? h : 256 + h);   // 0..7 | 264..271
        vsI[row][idx] = 0.f; vsP[row][idx] = 0.f;
        vsIP[row][idx] = 0.f; vsII[row][idx] = 0.f;
    }

    // ---- Stage V: vertical sliding window on column t ----
    {
        const float* __restrict__ Ic = I + pl*PLANE + t;
        const float* __restrict__ Pc = p + pl*PLANE + t;

        float sI = 0.f, sP = 0.f, sIP = 0.f, sII = 0.f;
        #pragma unroll
        for (int dy = -R; dy <= R; dy++) {
            const int y = k0 + dy;
            if (y >= 0 && y <= LH - 1) {
                const float vi = Ic[y*LW], vp = Pc[y*LW];
                sI += vi; sP += vp; sIP += vi*vp; sII += vi*vi;
            }
        }
        vsI[0][8+t] = sI; vsP[0][8+t] = sP; vsIP[0][8+t] = sIP; vsII[0][8+t] = sII;

        #pragma unroll
        for (int j = 1; j < KROWS; j++) {
            const int yo = k0 + j;                    // <= 255
            const int ya = yo + R;                    // add row
            if (ya <= LH - 1) {
                const float vi = Ic[ya*LW], vp = Pc[ya*LW];
                sI += vi; sP += vp; sIP += vi*vp; sII += vi*vi;
            }
            const int ys = yo - R - 1;                // drop row
            if (ys >= 0) {
                const float vi = Ic[ys*LW], vp = Pc[ys*LW];
                sI -= vi; sP -= vp; sIP -= vi*vp; sII -= vi*vi;
            }
            vsI[j][8+t] = sI; vsP[j][8+t] = sP; vsIP[j][8+t] = sIP; vsII[j][8+t] = sII;
        }
    }
    __syncthreads();

    // ---- Stage H: one unit (row, 4 cols) per thread + solve + store ----
    {
        const int row = t >> 6;                // 0..3
        const int xb  = (t & 63) << 2;         // 0..252

        const int ar = k0 + row;
        const float cy = (float)(min(ar + R, LH-1) - max(ar - R, 0) + 1);

        float wI[4], wP[4], wIP[4], wII[4];
#define HW(SRC, W)                                                              \
        {                                                                       \
            const float* b = &SRC[row][xb];                                     \
            const float4 q0 = *reinterpret_cast<const float4*>(b);              \
            const float4 q1 = *reinterpret_cast<const float4*>(b + 4);          \
            const float4 q2 = *reinterpret_cast<const float4*>(b + 8);          \
            const float4 q3 = *reinterpret_cast<const float4*>(b + 12);         \
            const float4 q4 = *reinterpret_cast<const float4*>(b + 16);         \
            W[0] = q0.x+q0.y+q0.z+q0.w + q1.x+q1.y+q1.z+q1.w                    \
                 + q2.x+q2.y+q2.z+q2.w + q3.x+q3.y+q3.z+q3.w + q4.x;            \
            W[1] = W[0] - q0.x + q4.y;                                          \
            W[2] = W[1] - q0.y + q4.z;                                          \
            W[3] = W[2] - q0.z + q4.w;                                          \
        }
        HW(vsI,  wI)
        HW(vsP,  wP)
        HW(vsIP, wIP)
        HW(vsII, wII)
#undef HW

        float2 ab[4];
        #pragma unroll
        for (int cc = 0; cc < 4; cc++) {
            const int c = xb + cc;
            const float cx  = (float)(min(c + R, LW-1) - max(c - R, 0) + 1);
            const float inv = 1.0f / (cx * cy);
            const float mI = wI[cc]*inv;
            const float mP = wP[cc]*inv;
            const float A  = (wIP[cc]*inv - mI*mP) / ((wII[cc]*inv - mI*mI) + EPSF);
            ab[cc] = make_float2(A, mP - A*mI);
        }
        float2* __restrict__ dst = g_AB + pl*PLANE + ar*LW + xb;
        *reinterpret_cast<float4*>(dst)     = make_float4(ab[0].x, ab[0].y, ab[1].x, ab[1].y);
        *reinterpret_cast<float4*>(dst + 2) = make_float4(ab[2].x, ab[2].y, ab[3].x, ab[3].y);
    }
}

// ---------------------------------------------------------------------------
// Kernel 2: x4 bilinear upsample (half-pixel, edge clamp == jax linear) + apply.
// Block m covers LR rows k0=2m, 2m+1 -> HR rows 8m..8m+7 (LR rows 2m-1..2m+2).
// 256 threads; each thread -> 8x4 = 32 output px (8 independent float4 ld/st).
// Grid = (128, NC).
// ---------------------------------------------------------------------------
__global__ void __launch_bounds__(256) k_apply(
    const float* __restrict__ Ihr, float* __restrict__ out)
{
    __shared__ float2 sAB[4][LW];

    const int m  = blockIdx.x;        // 0..127
    const int pl = blockIdx.y;
    const int t  = threadIdx.x;
    const int k0 = m << 1;

    const int r0 = max(k0 - 1, 0);
    const int r3 = min(k0 + 2, LH - 1);

    const float2* __restrict__ AB = g_AB + pl*PLANE;
    sAB[0][t] = AB[r0     *LW + t];
    sAB[1][t] = AB[ k0    *LW + t];
    sAB[2][t] = AB[(k0+1) *LW + t];
    sAB[3][t] = AB[r3     *LW + t];
    __syncthreads();

    const int xm = max(t - 1, 0);
    const int xp = min(t + 1, LW - 1);

    float xA[4][4], xB[4][4];
    #pragma unroll
    for (int j = 0; j < 4; j++) {
        const float2 vm = sAB[j][xm], v0 = sAB[j][t], vp = sAB[j][xp];
        xA[j][0] = 0.375f*vm.x + 0.625f*v0.x;  xB[j][0] = 0.375f*vm.y + 0.625f*v0.y;
        xA[j][1] = 0.125f*vm.x + 0.875f*v0.x;  xB[j][1] = 0.125f*vm.y + 0.875f*v0.y;
        xA[j][2] = 0.875f*v0.x + 0.125f*vp.x;  xB[j][2] = 0.875f*v0.y + 0.125f*vp.y;
        xA[j][3] = 0.625f*v0.x + 0.375f*vp.x;  xB[j][3] = 0.625f*v0.y + 0.375f*vp.y;
    }

    const int base = ((pl << 10) + (m << 3)) * 1024 + (t << 2);

    float4 iv[8];
    #pragma unroll
    for (int i = 0; i < 8; i++)
        iv[i] = __ldcs(reinterpret_cast<const float4*>(Ihr + base + i*1024));

    // HR row 8m+i uses smem rows (J0,J1) with weights (W0,W1):
    //   i=0:(0,1,.375,.625) 1:(0,1,.125,.875) 2:(1,2,.875,.125) 3:(1,2,.625,.375)
    //   i=4:(1,2,.375,.625) 5:(1,2,.125,.875) 6:(2,3,.875,.125) 7:(2,3,.625,.375)
#define OUTV(i, W0, J0, W1, J1)                                                 \
    {                                                                           \
        float4 ov;                                                              \
        ov.x = (W0*xA[J0][0] + W1*xA[J1][0])*iv[i].x + (W0*xB[J0][0] + W1*xB[J1][0]); \
        ov.y = (W0*xA[J0][1] + W1*xA[J1][1])*iv[i].y + (W0*xB[J0][1] + W1*xB[J1][1]); \
        ov.z = (W0*xA[J0][2] + W1*xA[J1][2])*iv[i].z + (W0*xB[J0][2] + W1*xB[J1][2]); \
        ov.w = (W0*xA[J0][3] + W1*xA[J1][3])*iv[i].w + (W0*xB[J0][3] + W1*xB[J1][3]); \
        __stcs(reinterpret_cast<float4*>(out + base + (i)*1024), ov);           \
    }
    OUTV(0, 0.375f, 0, 0.625f, 1)
    OUTV(1, 0.125f, 0, 0.875f, 1)
    OUTV(2, 0.875f, 1, 0.125f, 2)
    OUTV(3, 0.625f, 1, 0.375f, 2)
    OUTV(4, 0.375f, 1, 0.625f, 2)
    OUTV(5, 0.125f, 1, 0.875f, 2)
    OUTV(6, 0.875f, 2, 0.125f, 3)
    OUTV(7, 0.625f, 2, 0.375f, 3)
#undef OUTV
}

// ---------------------------------------------------------------------------
extern "C" void kernel_launch(void* const* d_in, const int* in_sizes, int n_in,
                              void* d_out, int out_size)
{
    const float* p_lr = (const float*)d_in[0];
    const float* I_lr = (const float*)d_in[1];
    const float* I_hr = (const float*)d_in[2];
    float* out = (float*)d_out;

    k_AB   <<<dim3(LH/KROWS, NC), 256>>>(p_lr, I_lr);
    k_apply<<<dim3(LH/2,     NC), 256>>>(I_hr, out);
}